// round 1
// baseline (speedup 1.0000x reference)
#include <cuda_runtime.h>

#define N_USERS 100000
#define N_ITEMS 50000
#define N_NODES 150000
#define NNZ     2000000
#define EMB     100
#define BATCH   16384

// ---------------- scratch (static device globals; no allocs allowed) -------
__device__ float g_e1[N_NODES * EMB];   // 60 MB
__device__ float g_e2[N_NODES * EMB];   // 60 MB
__device__ int   g_rowptr[N_NODES + 1];
__device__ int   g_deg[N_NODES];
__device__ int   g_cursor[N_NODES];
__device__ int   g_ccol[NNZ];
__device__ float g_cval[NNZ];

// ---------------- CSR build ------------------------------------------------
__global__ void k_zero_deg() {
    int i = blockIdx.x * blockDim.x + threadIdx.x;
    if (i < N_NODES) g_deg[i] = 0;
}

__global__ void k_hist(const int* __restrict__ row) {
    int i = blockIdx.x * blockDim.x + threadIdx.x;
    if (i < NNZ) atomicAdd(&g_deg[row[i]], 1);
}

// single-block exclusive scan over 150000 degrees -> rowptr + cursor
__global__ void k_scan() {
    __shared__ int part[1024];
    int tid = threadIdx.x;
    const int CH = (N_NODES + 1023) / 1024;   // 147
    int base = tid * CH;
    int s = 0;
    for (int i = 0; i < CH; i++) {
        int idx = base + i;
        if (idx < N_NODES) s += g_deg[idx];
    }
    part[tid] = s;
    __syncthreads();
    // Hillis-Steele inclusive scan over 1024 partials
    for (int off = 1; off < 1024; off <<= 1) {
        int v = (tid >= off) ? part[tid - off] : 0;
        __syncthreads();
        part[tid] += v;
        __syncthreads();
    }
    int run = (tid == 0) ? 0 : part[tid - 1];   // exclusive prefix of this chunk
    for (int i = 0; i < CH; i++) {
        int idx = base + i;
        if (idx < N_NODES) {
            g_rowptr[idx] = run;
            g_cursor[idx] = run;
            run += g_deg[idx];
        }
    }
    if (tid == 1023) g_rowptr[N_NODES] = part[1023];   // == NNZ
}

__global__ void k_scatter(const int* __restrict__ row, const int* __restrict__ col,
                          const float* __restrict__ val) {
    int i = blockIdx.x * blockDim.x + threadIdx.x;
    if (i < NNZ) {
        int r   = row[i];
        int pos = atomicAdd(&g_cursor[r], 1);
        g_ccol[pos] = col[i];
        g_cval[pos] = val[i];
    }
}

// ---------------- SpMM: warp per row, gather form (no float atomics) -------
// LAYER1: x = ego (split across user_emb/item_emb), y = g_e1
// else  : x = g_e1,                                 y = g_e2
template <bool LAYER1>
__global__ void k_spmm(const float* __restrict__ ue, const float* __restrict__ ie) {
    int row  = (blockIdx.x * blockDim.x + threadIdx.x) >> 5;
    int lane = threadIdx.x & 31;
    if (row >= N_NODES) return;

    const float* __restrict__ x = LAYER1 ? nullptr : g_e1;
    float* __restrict__ y       = LAYER1 ? g_e1 : g_e2;

    auto srcrow = [&](int c) -> const float* {
        if (LAYER1)
            return (c < N_USERS) ? (ue + (long)c * EMB)
                                 : (ie + (long)(c - N_USERS) * EMB);
        return x + (long)c * EMB;
    };

    float a0 = 0.f, a1 = 0.f, a2 = 0.f, a3 = 0.f;
    int s = g_rowptr[row], e = g_rowptr[row + 1];
    int p = s;
    for (; p + 1 < e; p += 2) {
        int   c0 = __ldg(&g_ccol[p]);
        int   c1 = __ldg(&g_ccol[p + 1]);
        float v0 = __ldg(&g_cval[p]);
        float v1 = __ldg(&g_cval[p + 1]);
        const float* x0 = srcrow(c0);
        const float* x1 = srcrow(c1);
        float b00 = x0[lane], b01 = x0[lane + 32], b02 = x0[lane + 64];
        float b10 = x1[lane], b11 = x1[lane + 32], b12 = x1[lane + 64];
        float b03 = 0.f, b13 = 0.f;
        if (lane < 4) { b03 = x0[lane + 96]; b13 = x1[lane + 96]; }
        a0 = fmaf(v0, b00, fmaf(v1, b10, a0));
        a1 = fmaf(v0, b01, fmaf(v1, b11, a1));
        a2 = fmaf(v0, b02, fmaf(v1, b12, a2));
        a3 = fmaf(v0, b03, fmaf(v1, b13, a3));
    }
    if (p < e) {
        int   c = __ldg(&g_ccol[p]);
        float v = __ldg(&g_cval[p]);
        const float* x0 = srcrow(c);
        a0 = fmaf(v, x0[lane], a0);
        a1 = fmaf(v, x0[lane + 32], a1);
        a2 = fmaf(v, x0[lane + 64], a2);
        if (lane < 4) a3 = fmaf(v, x0[lane + 96], a3);
    }
    float* yr = y + (long)row * EMB;
    yr[lane]      = a0;
    yr[lane + 32] = a1;
    yr[lane + 64] = a2;
    if (lane < 4) yr[lane + 96] = a3;
}

// ---------------- fused gather + mean + MLP --------------------------------
// one thread per batch element; W1/W2/W3 staged in dynamic smem (broadcast reads)
__global__ void k_mlp(const float* __restrict__ ue, const float* __restrict__ ie,
                      const int* __restrict__ uidx, const int* __restrict__ iidx,
                      const float* __restrict__ W1, const float* __restrict__ b1,
                      const float* __restrict__ W2, const float* __restrict__ b2,
                      const float* __restrict__ W3, const float* __restrict__ b3,
                      float* __restrict__ out) {
    extern __shared__ float sm[];
    float* sW1 = sm;                 // 200*64 = 12800
    float* sW2 = sW1 + 12800;        // 64*32  = 2048
    float* sb1 = sW2 + 2048;         // 64
    float* sW3 = sb1 + 64;           // 32
    float* sb2 = sW3 + 32;           // 32

    int tid = threadIdx.x;
    for (int i = tid; i < 12800; i += blockDim.x) sW1[i] = W1[i];
    for (int i = tid; i < 2048;  i += blockDim.x) sW2[i] = W2[i];
    if (tid < 64) sb1[tid] = b1[tid];
    if (tid < 32) { sW3[tid] = W3[tid]; sb2[tid] = b2[tid]; }
    __syncthreads();

    int b = blockIdx.x * blockDim.x + tid;
    if (b >= BATCH) return;

    int u  = uidx[b];
    int it = iidx[b];
    const float* pu0 = ue   + (long)u * EMB;
    const float* pu1 = g_e1 + (long)u * EMB;
    const float* pu2 = g_e2 + (long)u * EMB;
    const float* pi0 = ie   + (long)it * EMB;
    const float* pi1 = g_e1 + (long)(it + N_USERS) * EMB;
    const float* pi2 = g_e2 + (long)(it + N_USERS) * EMB;

    const float third = 1.0f / 3.0f;
    float acc[64];
#pragma unroll
    for (int j = 0; j < 64; j++) acc[j] = sb1[j];

    for (int k = 0; k < EMB; k++) {
        float xk = (pu0[k] + pu1[k] + pu2[k]) * third;
        const float4* wr = (const float4*)(sW1 + k * 64);
#pragma unroll
        for (int j4 = 0; j4 < 16; j4++) {
            float4 w = wr[j4];
            acc[4 * j4 + 0] = fmaf(xk, w.x, acc[4 * j4 + 0]);
            acc[4 * j4 + 1] = fmaf(xk, w.y, acc[4 * j4 + 1]);
            acc[4 * j4 + 2] = fmaf(xk, w.z, acc[4 * j4 + 2]);
            acc[4 * j4 + 3] = fmaf(xk, w.w, acc[4 * j4 + 3]);
        }
    }
    for (int k = 0; k < EMB; k++) {
        float xk = (pi0[k] + pi1[k] + pi2[k]) * third;
        const float4* wr = (const float4*)(sW1 + (EMB + k) * 64);
#pragma unroll
        for (int j4 = 0; j4 < 16; j4++) {
            float4 w = wr[j4];
            acc[4 * j4 + 0] = fmaf(xk, w.x, acc[4 * j4 + 0]);
            acc[4 * j4 + 1] = fmaf(xk, w.y, acc[4 * j4 + 1]);
            acc[4 * j4 + 2] = fmaf(xk, w.z, acc[4 * j4 + 2]);
            acc[4 * j4 + 3] = fmaf(xk, w.w, acc[4 * j4 + 3]);
        }
    }

    float acc2[32];
#pragma unroll
    for (int j = 0; j < 32; j++) acc2[j] = sb2[j];
#pragma unroll
    for (int k = 0; k < 64; k++) {
        float hk = fmaxf(acc[k], 0.0f);
        const float4* wr = (const float4*)(sW2 + k * 32);
#pragma unroll
        for (int j4 = 0; j4 < 8; j4++) {
            float4 w = wr[j4];
            acc2[4 * j4 + 0] = fmaf(hk, w.x, acc2[4 * j4 + 0]);
            acc2[4 * j4 + 1] = fmaf(hk, w.y, acc2[4 * j4 + 1]);
            acc2[4 * j4 + 2] = fmaf(hk, w.z, acc2[4 * j4 + 2]);
            acc2[4 * j4 + 3] = fmaf(hk, w.w, acc2[4 * j4 + 3]);
        }
    }

    float o = __ldg(&b3[0]);
#pragma unroll
    for (int k = 0; k < 32; k++) o = fmaf(acc2[k], sW3[k], o);
    out[b] = o;
}

// ---------------- launch ---------------------------------------------------
extern "C" void kernel_launch(void* const* d_in, const int* in_sizes, int n_in,
                              void* d_out, int out_size) {
    const float* ue   = (const float*)d_in[0];
    const float* ie   = (const float*)d_in[1];
    const int*   arow = (const int*)d_in[2];
    const int*   acol = (const int*)d_in[3];
    const float* aval = (const float*)d_in[4];
    const int*   uidx = (const int*)d_in[5];
    const int*   iidx = (const int*)d_in[6];
    const float* W1   = (const float*)d_in[7];
    const float* b1   = (const float*)d_in[8];
    const float* W2   = (const float*)d_in[9];
    const float* b2   = (const float*)d_in[10];
    const float* W3   = (const float*)d_in[11];
    const float* b3   = (const float*)d_in[12];
    float*       out  = (float*)d_out;

    // CSR build (every call; deterministic work)
    k_zero_deg<<<(N_NODES + 255) / 256, 256>>>();
    k_hist<<<(NNZ + 255) / 256, 256>>>(arow);
    k_scan<<<1, 1024>>>();
    k_scatter<<<(NNZ + 255) / 256, 256>>>(arow, acol, aval);

    // two propagation layers (warp per row)
    const int spmm_blocks = (N_NODES * 32 + 255) / 256;
    k_spmm<true><<<spmm_blocks, 256>>>(ue, ie);
    k_spmm<false><<<spmm_blocks, 256>>>(ue, ie);

    // fused gather + mean + MLP
    const int smem_bytes = (12800 + 2048 + 64 + 32 + 32) * (int)sizeof(float);
    cudaFuncSetAttribute(k_mlp, cudaFuncAttributeMaxDynamicSharedMemorySize, smem_bytes);
    k_mlp<<<BATCH / 128, 128, smem_bytes>>>(ue, ie, uidx, iidx,
                                            W1, b1, W2, b2, W3, b3, out);
}

// round 2
// speedup vs baseline: 1.1182x; 1.1182x over previous
#include <cuda_runtime.h>

#define N_USERS 100000
#define N_ITEMS 50000
#define N_NODES 150000
#define NNZ     2000000
#define EMB     100
#define BATCH   16384

// ---------------- scratch (static device globals; no allocs allowed) -------
__device__ float g_e1[N_NODES * EMB];     // 60 MB : layer-1 embeddings (all nodes)
__device__ float g_bu2[BATCH * EMB];      // 6.5 MB: layer-2 at batch user rows
__device__ float g_bi2[BATCH * EMB];      // 6.5 MB: layer-2 at batch item rows
__device__ int   g_rowptr[N_NODES + 1];
__device__ int   g_deg[N_NODES];
__device__ int   g_cursor[N_NODES];
__device__ int2  g_edges[NNZ];            // {col, bitcast(val)} interleaved

// ---------------- CSR build ------------------------------------------------
__global__ void k_zero_deg() {
    int i = blockIdx.x * blockDim.x + threadIdx.x;
    if (i < N_NODES) g_deg[i] = 0;
}

__global__ void k_hist(const int* __restrict__ row) {
    int i = blockIdx.x * blockDim.x + threadIdx.x;
    if (i < NNZ) atomicAdd(&g_deg[row[i]], 1);
}

// single-block exclusive scan over 150000 degrees -> rowptr + cursor
__global__ void k_scan() {
    __shared__ int part[1024];
    int tid = threadIdx.x;
    const int CH = (N_NODES + 1023) / 1024;   // 147
    int base = tid * CH;
    int s = 0;
    for (int i = 0; i < CH; i++) {
        int idx = base + i;
        if (idx < N_NODES) s += g_deg[idx];
    }
    part[tid] = s;
    __syncthreads();
    for (int off = 1; off < 1024; off <<= 1) {
        int v = (tid >= off) ? part[tid - off] : 0;
        __syncthreads();
        part[tid] += v;
        __syncthreads();
    }
    int run = (tid == 0) ? 0 : part[tid - 1];
    for (int i = 0; i < CH; i++) {
        int idx = base + i;
        if (idx < N_NODES) {
            g_rowptr[idx] = run;
            g_cursor[idx] = run;
            run += g_deg[idx];
        }
    }
    if (tid == 1023) g_rowptr[N_NODES] = part[1023];
}

__global__ void k_scatter(const int* __restrict__ row, const int* __restrict__ col,
                          const float* __restrict__ val) {
    int i = blockIdx.x * blockDim.x + threadIdx.x;
    if (i < NNZ) {
        int r   = row[i];
        int pos = atomicAdd(&g_cursor[r], 1);
        int2 ed;
        ed.x = col[i];
        ed.y = __float_as_int(val[i]);
        g_edges[pos] = ed;
    }
}

// ---------------- layer-1 SpMM: warp per row, float4 gather ----------------
// y = A @ ego for ALL nodes (needed as gather source for layer 2).
__global__ __launch_bounds__(256)
void k_spmm1(const float* __restrict__ ue, const float* __restrict__ ie) {
    int row  = (blockIdx.x * blockDim.x + threadIdx.x) >> 5;
    int lane = threadIdx.x & 31;
    if (row >= N_NODES) return;

    float4 acc = make_float4(0.f, 0.f, 0.f, 0.f);
    int s = g_rowptr[row], e = g_rowptr[row + 1];
    int p = s;
    for (; p + 1 < e; p += 2) {
        int2 e0 = __ldg(&g_edges[p]);
        int2 e1 = __ldg(&g_edges[p + 1]);
        float v0 = __int_as_float(e0.y);
        float v1 = __int_as_float(e1.y);
        const float4* x0 = (const float4*)((e0.x < N_USERS)
                            ? (ue + (long)e0.x * EMB)
                            : (ie + (long)(e0.x - N_USERS) * EMB));
        const float4* x1 = (const float4*)((e1.x < N_USERS)
                            ? (ue + (long)e1.x * EMB)
                            : (ie + (long)(e1.x - N_USERS) * EMB));
        if (lane < 25) {
            float4 a = __ldg(&x0[lane]);
            float4 b = __ldg(&x1[lane]);
            acc.x = fmaf(v0, a.x, fmaf(v1, b.x, acc.x));
            acc.y = fmaf(v0, a.y, fmaf(v1, b.y, acc.y));
            acc.z = fmaf(v0, a.z, fmaf(v1, b.z, acc.z));
            acc.w = fmaf(v0, a.w, fmaf(v1, b.w, acc.w));
        }
    }
    if (p < e) {
        int2 e0 = __ldg(&g_edges[p]);
        float v0 = __int_as_float(e0.y);
        const float4* x0 = (const float4*)((e0.x < N_USERS)
                            ? (ue + (long)e0.x * EMB)
                            : (ie + (long)(e0.x - N_USERS) * EMB));
        if (lane < 25) {
            float4 a = __ldg(&x0[lane]);
            acc.x = fmaf(v0, a.x, acc.x);
            acc.y = fmaf(v0, a.y, acc.y);
            acc.z = fmaf(v0, a.z, acc.z);
            acc.w = fmaf(v0, a.w, acc.w);
        }
    }
    if (lane < 25)
        ((float4*)(g_e1 + (long)row * EMB))[lane] = acc;
}

// ---------------- layer-2 restricted to batch rows -------------------------
// warp w < BATCH      : node = uidx[w],           out = g_bu2 + w*EMB
// warp w >= BATCH     : node = iidx[w-B]+N_USERS, out = g_bi2 + (w-B)*EMB
__global__ __launch_bounds__(256)
void k_batch2(const int* __restrict__ uidx, const int* __restrict__ iidx) {
    int w    = (blockIdx.x * blockDim.x + threadIdx.x) >> 5;
    int lane = threadIdx.x & 31;
    if (w >= 2 * BATCH) return;

    int node;
    float* out;
    if (w < BATCH) {
        node = __ldg(&uidx[w]);
        out  = g_bu2 + (long)w * EMB;
    } else {
        node = __ldg(&iidx[w - BATCH]) + N_USERS;
        out  = g_bi2 + (long)(w - BATCH) * EMB;
    }

    float4 acc = make_float4(0.f, 0.f, 0.f, 0.f);
    int s = g_rowptr[node], e = g_rowptr[node + 1];
    int p = s;
    for (; p + 1 < e; p += 2) {
        int2 e0 = __ldg(&g_edges[p]);
        int2 e1 = __ldg(&g_edges[p + 1]);
        float v0 = __int_as_float(e0.y);
        float v1 = __int_as_float(e1.y);
        const float4* x0 = (const float4*)(g_e1 + (long)e0.x * EMB);
        const float4* x1 = (const float4*)(g_e1 + (long)e1.x * EMB);
        if (lane < 25) {
            float4 a = __ldg(&x0[lane]);
            float4 b = __ldg(&x1[lane]);
            acc.x = fmaf(v0, a.x, fmaf(v1, b.x, acc.x));
            acc.y = fmaf(v0, a.y, fmaf(v1, b.y, acc.y));
            acc.z = fmaf(v0, a.z, fmaf(v1, b.z, acc.z));
            acc.w = fmaf(v0, a.w, fmaf(v1, b.w, acc.w));
        }
    }
    if (p < e) {
        int2 e0 = __ldg(&g_edges[p]);
        float v0 = __int_as_float(e0.y);
        const float4* x0 = (const float4*)(g_e1 + (long)e0.x * EMB);
        if (lane < 25) {
            float4 a = __ldg(&x0[lane]);
            acc.x = fmaf(v0, a.x, acc.x);
            acc.y = fmaf(v0, a.y, acc.y);
            acc.z = fmaf(v0, a.z, acc.z);
            acc.w = fmaf(v0, a.w, acc.w);
        }
    }
    if (lane < 25)
        ((float4*)out)[lane] = acc;
}

// ---------------- fused gather + mean + MLP --------------------------------
__global__ void k_mlp(const float* __restrict__ ue, const float* __restrict__ ie,
                      const int* __restrict__ uidx, const int* __restrict__ iidx,
                      const float* __restrict__ W1, const float* __restrict__ b1,
                      const float* __restrict__ W2, const float* __restrict__ b2,
                      const float* __restrict__ W3, const float* __restrict__ b3,
                      float* __restrict__ out) {
    extern __shared__ float sm[];
    float* sW1 = sm;                 // 200*64 = 12800
    float* sW2 = sW1 + 12800;        // 64*32  = 2048
    float* sb1 = sW2 + 2048;         // 64
    float* sW3 = sb1 + 64;           // 32
    float* sb2 = sW3 + 32;           // 32

    int tid = threadIdx.x;
    for (int i = tid; i < 12800; i += blockDim.x) sW1[i] = W1[i];
    for (int i = tid; i < 2048;  i += blockDim.x) sW2[i] = W2[i];
    if (tid < 64) sb1[tid] = b1[tid];
    if (tid < 32) { sW3[tid] = W3[tid]; sb2[tid] = b2[tid]; }
    __syncthreads();

    int b = blockIdx.x * blockDim.x + tid;
    if (b >= BATCH) return;

    int u  = uidx[b];
    int it = iidx[b];
    const float* pu0 = ue    + (long)u * EMB;
    const float* pu1 = g_e1  + (long)u * EMB;
    const float* pu2 = g_bu2 + (long)b * EMB;
    const float* pi0 = ie    + (long)it * EMB;
    const float* pi1 = g_e1  + (long)(it + N_USERS) * EMB;
    const float* pi2 = g_bi2 + (long)b * EMB;

    const float third = 1.0f / 3.0f;
    float acc[64];
#pragma unroll
    for (int j = 0; j < 64; j++) acc[j] = sb1[j];

    for (int k = 0; k < EMB; k++) {
        float xk = (pu0[k] + pu1[k] + pu2[k]) * third;
        const float4* wr = (const float4*)(sW1 + k * 64);
#pragma unroll
        for (int j4 = 0; j4 < 16; j4++) {
            float4 w = wr[j4];
            acc[4 * j4 + 0] = fmaf(xk, w.x, acc[4 * j4 + 0]);
            acc[4 * j4 + 1] = fmaf(xk, w.y, acc[4 * j4 + 1]);
            acc[4 * j4 + 2] = fmaf(xk, w.z, acc[4 * j4 + 2]);
            acc[4 * j4 + 3] = fmaf(xk, w.w, acc[4 * j4 + 3]);
        }
    }
    for (int k = 0; k < EMB; k++) {
        float xk = (pi0[k] + pi1[k] + pi2[k]) * third;
        const float4* wr = (const float4*)(sW1 + (EMB + k) * 64);
#pragma unroll
        for (int j4 = 0; j4 < 16; j4++) {
            float4 w = wr[j4];
            acc[4 * j4 + 0] = fmaf(xk, w.x, acc[4 * j4 + 0]);
            acc[4 * j4 + 1] = fmaf(xk, w.y, acc[4 * j4 + 1]);
            acc[4 * j4 + 2] = fmaf(xk, w.z, acc[4 * j4 + 2]);
            acc[4 * j4 + 3] = fmaf(xk, w.w, acc[4 * j4 + 3]);
        }
    }

    float acc2[32];
#pragma unroll
    for (int j = 0; j < 32; j++) acc2[j] = sb2[j];
#pragma unroll
    for (int k = 0; k < 64; k++) {
        float hk = fmaxf(acc[k], 0.0f);
        const float4* wr = (const float4*)(sW2 + k * 32);
#pragma unroll
        for (int j4 = 0; j4 < 8; j4++) {
            float4 w = wr[j4];
            acc2[4 * j4 + 0] = fmaf(hk, w.x, acc2[4 * j4 + 0]);
            acc2[4 * j4 + 1] = fmaf(hk, w.y, acc2[4 * j4 + 1]);
            acc2[4 * j4 + 2] = fmaf(hk, w.z, acc2[4 * j4 + 2]);
            acc2[4 * j4 + 3] = fmaf(hk, w.w, acc2[4 * j4 + 3]);
        }
    }

    float o = __ldg(&b3[0]);
#pragma unroll
    for (int k = 0; k < 32; k++) o = fmaf(acc2[k], sW3[k], o);
    out[b] = o;
}

// ---------------- launch ---------------------------------------------------
extern "C" void kernel_launch(void* const* d_in, const int* in_sizes, int n_in,
                              void* d_out, int out_size) {
    const float* ue   = (const float*)d_in[0];
    const float* ie   = (const float*)d_in[1];
    const int*   arow = (const int*)d_in[2];
    const int*   acol = (const int*)d_in[3];
    const float* aval = (const float*)d_in[4];
    const int*   uidx = (const int*)d_in[5];
    const int*   iidx = (const int*)d_in[6];
    const float* W1   = (const float*)d_in[7];
    const float* b1   = (const float*)d_in[8];
    const float* W2   = (const float*)d_in[9];
    const float* b2   = (const float*)d_in[10];
    const float* W3   = (const float*)d_in[11];
    const float* b3   = (const float*)d_in[12];
    float*       out  = (float*)d_out;

    // CSR build
    k_zero_deg<<<(N_NODES + 255) / 256, 256>>>();
    k_hist<<<(NNZ + 255) / 256, 256>>>(arow);
    k_scan<<<1, 1024>>>();
    k_scatter<<<(NNZ + 255) / 256, 256>>>(arow, acol, aval);

    // layer 1 over all nodes (warp per row)
    k_spmm1<<<(N_NODES * 32 + 255) / 256, 256>>>(ue, ie);

    // layer 2 only at batch rows (warp per batch element, users + items)
    k_batch2<<<(2 * BATCH * 32 + 255) / 256, 256>>>(uidx, iidx);

    // fused gather + mean + MLP
    const int smem_bytes = (12800 + 2048 + 64 + 32 + 32) * (int)sizeof(float);
    cudaFuncSetAttribute(k_mlp, cudaFuncAttributeMaxDynamicSharedMemorySize, smem_bytes);
    k_mlp<<<BATCH / 128, 128, smem_bytes>>>(ue, ie, uidx, iidx,
                                            W1, b1, W2, b2, W3, b3, out);
}